// round 8
// baseline (speedup 1.0000x reference)
#include <cuda_runtime.h>
#include <cstdint>

#define Bq 2
#define Hq 8
#define Sq 2048
#define Dq 64
#define TEMP 8.0f

#define BM 128
#define BN 64
#define NT 256

// smem word offsets (uint32 words)
#define W_Q   0                      // q tf32 [128][68]
#define W_KT  8704                   // k^T tf32 [64][72]   ([d][t])
#define W_VH  13312                  // v^T hi bf16x2 [64][36] ([d][tpair])
#define W_VL  15616                  // v^T lo bf16x2 [64][36]
#define W_EH  17920                  // e hi bf16x2 [128][36] ([row][tpair])
#define W_EL  22528                  // e lo bf16x2 [128][36]
#define W_RS  27136                  // rowsum [2][128] floats
#define SMEM_WORDS 27392
#define SMEM_BYTES (SMEM_WORDS * 4)  // 109568 B -> 2 CTAs/SM

#define KTS 72     // KT row stride (words), pass A
#define EVS 36     // row stride (words) for VH/VL/EH/EL
#define KTBS 136   // pass-B KT row stride (words), buffer reuses E region

static __device__ __forceinline__ uint32_t f2tf32(float f) {
    uint32_t r;
    asm("cvt.rna.tf32.f32 %0, %1;" : "=r"(r) : "f"(f));
    return r;
}
static __device__ __forceinline__ uint32_t bf16x2(float hi, float lo) {
    uint32_t r;
    asm("cvt.rn.bf16x2.f32 %0, %1, %2;" : "=r"(r) : "f"(hi), "f"(lo));
    return r;
}
// exp(x) on fma/alu pipes only (no MUFU). Valid for |x| < ~80.
static __device__ __forceinline__ float fexp(float x) {
    const float L2E = 1.4426950408889634f;
    float t = fmaf(x, L2E, 12582912.0f);          // 1.5*2^23: rounds to int
    int   in = __float_as_int(t);
    float n  = t - 12582912.0f;
    float z  = fmaf(x, L2E, -n);                  // frac in [-0.5, 0.5]
    float w  = z * 0.6931471805599453f;
    float p  = fmaf(w, 8.3333333e-3f, 4.1666667e-2f);
    p = fmaf(p, w, 0.16666667f);
    p = fmaf(p, w, 0.5f);
    p = fmaf(p, w, 1.0f);
    p = fmaf(p, w, 1.0f);
    return __int_as_float(__float_as_int(p) + (in << 23));
}
static __device__ __forceinline__ void mma_tf32(float* d, const uint32_t* a,
                                                const uint32_t* b) {
    asm volatile(
        "mma.sync.aligned.m16n8k8.row.col.f32.tf32.tf32.f32 "
        "{%0,%1,%2,%3}, {%4,%5,%6,%7}, {%8,%9}, {%0,%1,%2,%3};"
        : "+f"(d[0]), "+f"(d[1]), "+f"(d[2]), "+f"(d[3])
        : "r"(a[0]), "r"(a[1]), "r"(a[2]), "r"(a[3]), "r"(b[0]), "r"(b[1]));
}
static __device__ __forceinline__ void mma_bf16(float* d, const uint32_t* a,
                                                const uint32_t* b) {
    asm volatile(
        "mma.sync.aligned.m16n8k16.row.col.f32.bf16.bf16.f32 "
        "{%0,%1,%2,%3}, {%4,%5,%6,%7}, {%8,%9}, {%0,%1,%2,%3};"
        : "+f"(d[0]), "+f"(d[1]), "+f"(d[2]), "+f"(d[3])
        : "r"(a[0]), "r"(a[1]), "r"(a[2]), "r"(a[3]), "r"(b[0]), "r"(b[1]));
}

__global__ __launch_bounds__(NT, 2)
void attn_mma_kernel(const float* __restrict__ q,
                     const float* __restrict__ k,
                     const float* __restrict__ v,
                     const float* __restrict__ cov,
                     const float* __restrict__ lambda_w,
                     const int*   __restrict__ mask,
                     float* __restrict__ out,      // [B,H,S,D]
                     float* __restrict__ attn)     // [B,H,S,S]
{
    extern __shared__ uint32_t sw[];
    uint32_t* QW  = sw + W_Q;
    uint32_t* KTW = sw + W_KT;
    uint32_t* VHW = sw + W_VH;
    uint32_t* VLW = sw + W_VL;
    uint32_t* EHW = sw + W_EH;
    uint32_t* ELW = sw + W_EL;
    uint32_t* KTB = sw + W_EH;      // pass-B KT buffer (E region is dead then)
    float*    rs  = (float*)(sw + W_RS);

    const int h     = blockIdx.x;   // innermost -> 8 heads share cov/mask in L2
    const int mtile = blockIdx.y;
    const int b     = blockIdx.z;
    const int bh    = b * Hq + h;
    const int tid   = threadIdx.x;
    const int wid   = tid >> 5;
    const int lane  = tid & 31;
    const int lg    = lane >> 2;    // group 0..7
    const int lt    = lane & 3;     // 0..3

    const int warp_m = wid & 3;     // row group (32 rows)
    const int warp_n = wid >> 2;    // 0..1: score col half / AV d half
    const int rm = warp_m * 32;
    const int cn = warp_n * 32;
    const int dn = warp_n * 32;

    const float lam  = lambda_w[h];
    const float wcov = lam / (lam + 1.0f);
    const float sqk  = 1.0f / ((lam + 1.0f) * TEMP);

    const float* qg    = q    + ((size_t)bh * Sq + (size_t)mtile * BM) * Dq;
    const float* kg    = k    + (size_t)bh * Sq * Dq;
    const float* vg    = v    + (size_t)bh * Sq * Dq;
    const float* covg  = cov  + ((size_t)b * Sq + (size_t)mtile * BM) * Sq;
    const int*   maskg = mask + ((size_t)b * Sq + (size_t)mtile * BM) * Sq;
    float*       attng = attn + ((size_t)bh * Sq + (size_t)mtile * BM) * Sq;
    float*       outg  = out  + ((size_t)bh * Sq + (size_t)mtile * BM) * Dq;

    // ---- fill q smem (tf32), once ----
    {
#pragma unroll
        for (int it = 0; it < 8; it++) {
            int idx = tid + it * NT;        // 2048 float4
            int r  = idx >> 4;
            int c4 = (idx & 15) << 2;
            float4 f = *(const float4*)&qg[r * Dq + c4];
            uint4 o;
            o.x = f2tf32(f.x); o.y = f2tf32(f.y);
            o.z = f2tf32(f.z); o.w = f2tf32(f.w);
            *(uint4*)&QW[r * 68 + c4] = o;
        }
    }

    float oacc[2][4][4];    // AV accumulators (32 rows x 32 d per warp)
#pragma unroll
    for (int mi = 0; mi < 2; mi++)
#pragma unroll
        for (int nf = 0; nf < 4; nf++)
#pragma unroll
            for (int c = 0; c < 4; c++) oacc[mi][nf][c] = 0.0f;
    float rowsum[4] = {0.0f, 0.0f, 0.0f, 0.0f};

    // ================= PASS A: rowsums + AV (no attn store) =================
    for (int nt = 0; nt < Sq / BN; nt++) {
        const int t0 = nt * BN;
        __syncthreads();   // protect k/v/e smem from previous AV reads

        // ---- fill k^T (tf32): 64 t x 64 d ----
#pragma unroll
        for (int it = 0; it < 4; it++) {
            int idx = tid + it * NT;        // 1024 float4
            int t  = idx & 63;
            int c4 = (idx >> 6) << 2;
            float4 f = *(const float4*)&kg[(size_t)(t0 + t) * Dq + c4];
            KTW[(c4 + 0) * KTS + t] = f2tf32(f.x);
            KTW[(c4 + 1) * KTS + t] = f2tf32(f.y);
            KTW[(c4 + 2) * KTS + t] = f2tf32(f.z);
            KTW[(c4 + 3) * KTS + t] = f2tf32(f.w);
        }
        // ---- fill v^T split-bf16 (paired t): 32 tp x 64 d ----
#pragma unroll
        for (int it = 0; it < 2; it++) {
            int idx = tid + it * NT;        // 512 items: 32 tp x 16 d4
            int tp = idx & 31;
            int d4 = (idx >> 5) << 2;
            float4 v0 = *(const float4*)&vg[(size_t)(t0 + 2 * tp) * Dq + d4];
            float4 v1 = *(const float4*)&vg[(size_t)(t0 + 2 * tp + 1) * Dq + d4];
            const float e0[4] = {v0.x, v0.y, v0.z, v0.w};
            const float e1[4] = {v1.x, v1.y, v1.z, v1.w};
#pragma unroll
            for (int i = 0; i < 4; i++) {
                uint32_t hp = bf16x2(e1[i], e0[i]);
                float f0 = __uint_as_float(hp << 16);
                float f1 = __uint_as_float(hp & 0xffff0000u);
                uint32_t lp = bf16x2(e1[i] - f1, e0[i] - f0);
                VHW[(d4 + i) * EVS + tp] = hp;
                VLW[(d4 + i) * EVS + tp] = lp;
            }
        }
        __syncthreads();

        // ---- scores: warp tile 32 rows x 32 cols, tf32 mma ----
        float acc[2][4][4];
#pragma unroll
        for (int mi = 0; mi < 2; mi++)
#pragma unroll
            for (int ni = 0; ni < 4; ni++)
#pragma unroll
                for (int c = 0; c < 4; c++) acc[mi][ni][c] = 0.0f;

#pragma unroll
        for (int ks = 0; ks < 8; ks++) {
            const int kd = ks * 8;
            uint32_t a[2][4], bb[4][2];
#pragma unroll
            for (int mi = 0; mi < 2; mi++) {
                const uint32_t* q0 = QW + (rm + mi * 16 + lg) * 68 + kd + lt;
                a[mi][0] = q0[0];
                a[mi][1] = q0[8 * 68];
                a[mi][2] = q0[4];
                a[mi][3] = q0[8 * 68 + 4];
            }
#pragma unroll
            for (int ni = 0; ni < 4; ni++) {
                const uint32_t* kp = KTW + (kd + lt) * KTS + cn + ni * 8 + lg;
                bb[ni][0] = kp[0];
                bb[ni][1] = kp[4 * KTS];
            }
#pragma unroll
            for (int mi = 0; mi < 2; mi++)
#pragma unroll
                for (int ni = 0; ni < 4; ni++)
                    mma_tf32(acc[mi][ni], a[mi], bb[ni]);
        }

        // ---- epilogue: blend, mask, exp, rowsum, pack e to smem ----
#pragma unroll
        for (int mi = 0; mi < 2; mi++) {
#pragma unroll
            for (int rh = 0; rh < 2; rh++) {
                const int r = rm + mi * 16 + lg + rh * 8;
                const float* cr = covg  + (size_t)r * Sq + t0;
                const int*   mr = maskg + (size_t)r * Sq + t0;
                uint32_t* ehr = EHW + r * EVS;
                uint32_t* elr = ELW + r * EVS;
                float rsacc = 0.0f;
#pragma unroll
                for (int ni = 0; ni < 4; ni++) {
                    const int c = cn + ni * 8 + 2 * lt;
                    float s0 = acc[mi][ni][rh * 2 + 0];
                    float s1 = acc[mi][ni][rh * 2 + 1];
                    float2 cv = *(const float2*)(cr + c);
                    int2   mv = *(const int2*)(mr + c);
                    float e0 = mv.x ? fexp(fmaf(sqk, s0, wcov * cv.x)) : 0.0f;
                    float e1 = mv.y ? fexp(fmaf(sqk, s1, wcov * cv.y)) : 0.0f;
                    rsacc += e0 + e1;
                    uint32_t hp = bf16x2(e1, e0);
                    float f0 = __uint_as_float(hp << 16);
                    float f1 = __uint_as_float(hp & 0xffff0000u);
                    uint32_t lp = bf16x2(e1 - f1, e0 - f0);
                    const int tpl = c >> 1;
                    ehr[tpl] = hp;
                    elr[tpl] = lp;
                }
                rowsum[mi * 2 + rh] += rsacc;
            }
        }
        __syncthreads();

        // ---- AV: warp tile 32 rows x 32 d, k=64 via 4 k16 steps ----
#pragma unroll
        for (int ks = 0; ks < 4; ks++) {
            const int tpb = ks * 8 + lt;
            uint32_t ah[2][4], al[2][4], bh[4][2], bl[4][2];
#pragma unroll
            for (int mi = 0; mi < 2; mi++) {
                const int base = (rm + mi * 16 + lg) * EVS + tpb;
                ah[mi][0] = EHW[base];
                ah[mi][1] = EHW[base + 8 * EVS];
                ah[mi][2] = EHW[base + 4];
                ah[mi][3] = EHW[base + 8 * EVS + 4];
                al[mi][0] = ELW[base];
                al[mi][1] = ELW[base + 8 * EVS];
                al[mi][2] = ELW[base + 4];
                al[mi][3] = ELW[base + 8 * EVS + 4];
            }
#pragma unroll
            for (int nf = 0; nf < 4; nf++) {
                const int base = (dn + nf * 8 + lg) * EVS + tpb;
                bh[nf][0] = VHW[base];
                bh[nf][1] = VHW[base + 4];
                bl[nf][0] = VLW[base];
                bl[nf][1] = VLW[base + 4];
            }
#pragma unroll
            for (int mi = 0; mi < 2; mi++)
#pragma unroll
                for (int nf = 0; nf < 4; nf++) {
                    mma_bf16(oacc[mi][nf], ah[mi], bh[nf]);
                    mma_bf16(oacc[mi][nf], ah[mi], bl[nf]);
                    mma_bf16(oacc[mi][nf], al[mi], bh[nf]);
                }
        }
    }

    // ---- rowsum: reduce over lane&3 (lanes sharing a row) ----
#pragma unroll
    for (int i = 0; i < 4; i++) {
        rowsum[i] += __shfl_xor_sync(0xffffffffu, rowsum[i], 1);
        rowsum[i] += __shfl_xor_sync(0xffffffffu, rowsum[i], 2);
    }
    if (lt == 0) {
#pragma unroll
        for (int mi = 0; mi < 2; mi++)
#pragma unroll
            for (int rh = 0; rh < 2; rh++)
                rs[warp_n * 128 + rm + mi * 16 + lg + rh * 8] = rowsum[mi * 2 + rh];
    }
    __syncthreads();

    // per-thread inverse rowsums for its 4 epilogue rows
    float iv4[4];
#pragma unroll
    for (int mi = 0; mi < 2; mi++)
#pragma unroll
        for (int rh = 0; rh < 2; rh++) {
            const int r = rm + mi * 16 + lg + rh * 8;
            iv4[mi * 2 + rh] = 1.0f / (rs[r] + rs[128 + r]);
        }

    // ---- write normalized output ----
#pragma unroll
    for (int mi = 0; mi < 2; mi++) {
#pragma unroll
        for (int rh = 0; rh < 2; rh++) {
            const int r = rm + mi * 16 + lg + rh * 8;
            const float iv = iv4[mi * 2 + rh];
#pragma unroll
            for (int nf = 0; nf < 4; nf++) {
                const int d = dn + nf * 8 + 2 * lt;
                float2 o;
                o.x = oacc[mi][nf][rh * 2 + 0] * iv;
                o.y = oacc[mi][nf][rh * 2 + 1] * iv;
                *(float2*)(outg + (size_t)r * Dq + d) = o;
            }
        }
    }

    // ============ PASS B: recompute scores, write normalized attn ============
    for (int nt = 0; nt < Sq / 128; nt++) {
        const int t0 = nt * 128;
        __syncthreads();   // protect KTB from previous iteration's reads

        // ---- fill k^T (tf32): 128 t x 64 d into KTB ----
#pragma unroll
        for (int it = 0; it < 8; it++) {
            int idx = tid + it * NT;        // 2048 float4
            int t  = idx & 127;
            int c4 = (idx >> 7) << 2;
            float4 f = *(const float4*)&kg[(size_t)(t0 + t) * Dq + c4];
            KTB[(c4 + 0) * KTBS + t] = f2tf32(f.x);
            KTB[(c4 + 1) * KTBS + t] = f2tf32(f.y);
            KTB[(c4 + 2) * KTBS + t] = f2tf32(f.z);
            KTB[(c4 + 3) * KTBS + t] = f2tf32(f.w);
        }
        __syncthreads();

        // two 32-col groups per warp (64-col half per warp_n)
#pragma unroll
        for (int g = 0; g < 2; g++) {
            const int cb = warp_n * 64 + g * 32;
            float acc[2][4][4];
#pragma unroll
            for (int mi = 0; mi < 2; mi++)
#pragma unroll
                for (int ni = 0; ni < 4; ni++)
#pragma unroll
                    for (int c = 0; c < 4; c++) acc[mi][ni][c] = 0.0f;

#pragma unroll
            for (int ks = 0; ks < 8; ks++) {
                const int kd = ks * 8;
                uint32_t a[2][4], bb[4][2];
#pragma unroll
                for (int mi = 0; mi < 2; mi++) {
                    const uint32_t* q0 = QW + (rm + mi * 16 + lg) * 68 + kd + lt;
                    a[mi][0] = q0[0];
                    a[mi][1] = q0[8 * 68];
                    a[mi][2] = q0[4];
                    a[mi][3] = q0[8 * 68 + 4];
                }
#pragma unroll
                for (int ni = 0; ni < 4; ni++) {
                    const uint32_t* kp = KTB + (kd + lt) * KTBS + cb + ni * 8 + lg;
                    bb[ni][0] = kp[0];
                    bb[ni][1] = kp[4 * KTBS];
                }
#pragma unroll
                for (int mi = 0; mi < 2; mi++)
#pragma unroll
                    for (int ni = 0; ni < 4; ni++)
                        mma_tf32(acc[mi][ni], a[mi], bb[ni]);
            }

            // epilogue: normalized attn store
#pragma unroll
            for (int mi = 0; mi < 2; mi++) {
#pragma unroll
                for (int rh = 0; rh < 2; rh++) {
                    const int r = rm + mi * 16 + lg + rh * 8;
                    const float iv = iv4[mi * 2 + rh];
                    const float* cr = covg  + (size_t)r * Sq + t0;
                    const int*   mr = maskg + (size_t)r * Sq + t0;
                    float*       ar = attng + (size_t)r * Sq + t0;
#pragma unroll
                    for (int ni = 0; ni < 4; ni++) {
                        const int c = cb + ni * 8 + 2 * lt;
                        float s0 = acc[mi][ni][rh * 2 + 0];
                        float s1 = acc[mi][ni][rh * 2 + 1];
                        float2 cv = *(const float2*)(cr + c);
                        int2   mv = *(const int2*)(mr + c);
                        float e0 = mv.x ? iv * fexp(fmaf(sqk, s0, wcov * cv.x)) : 0.0f;
                        float e1 = mv.y ? iv * fexp(fmaf(sqk, s1, wcov * cv.y)) : 0.0f;
                        *(float2*)(ar + c) = make_float2(e0, e1);
                    }
                }
            }
        }
    }
}

extern "C" void kernel_launch(void* const* d_in, const int* in_sizes, int n_in,
                              void* d_out, int out_size)
{
    const float* q    = (const float*)d_in[0];
    const float* k    = (const float*)d_in[1];
    const float* v    = (const float*)d_in[2];
    const float* cov  = (const float*)d_in[3];
    const float* lam  = (const float*)d_in[4];
    const int*   mask = (const int*)d_in[5];

    float* out  = (float*)d_out;                          // [B,H,S,D]
    float* attn = out + (size_t)Bq * Hq * Sq * Dq;        // [B,H,S,S]

    cudaFuncSetAttribute(attn_mma_kernel,
                         cudaFuncAttributeMaxDynamicSharedMemorySize, SMEM_BYTES);

    dim3 grid(Hq, Sq / BM, Bq);  // h innermost: heads share cov/mask in L2
    attn_mma_kernel<<<grid, NT, SMEM_BYTES>>>(q, k, v, cov, lam, mask, out, attn);
}

// round 9
// speedup vs baseline: 1.5887x; 1.5887x over previous
#include <cuda_runtime.h>
#include <cstdint>

#define Bq 2
#define Hq 8
#define Sq 2048
#define Dq 64
#define TEMP 8.0f

#define BM 128
#define BN 64
#define NT 256

// smem word offsets (uint32 words)
#define W_Q   0                      // q tf32 [128][68]
#define W_KT  8704                   // k^T tf32 [64][72]   ([d][t])
#define W_VH  13312                  // v^T hi bf16x2 [64][36] ([d][tpair])
#define W_VL  15616                  // v^T lo bf16x2 [64][36]
#define W_EH  17920                  // e hi bf16x2 [128][36] ([row][tpair])
#define W_EL  22528                  // e lo bf16x2 [128][36]
#define W_RS  27136                  // rowsum [2][128] floats
#define SMEM_WORDS 27392
#define SMEM_BYTES (SMEM_WORDS * 4)  // 109568 B -> 2 CTAs/SM

#define KTS 72     // KT row stride (words)
#define EVS 36     // row stride (words) for VH/VL/EH/EL

// masked-cov scratch: covm = mask ? cov : -3e4   (33.5 MB)
__device__ float g_covm[(size_t)Bq * Sq * Sq];

static __device__ __forceinline__ uint32_t f2tf32(float f) {
    uint32_t r;
    asm("cvt.rna.tf32.f32 %0, %1;" : "=r"(r) : "f"(f));
    return r;
}
static __device__ __forceinline__ uint32_t bf16x2(float hi, float lo) {
    uint32_t r;
    asm("cvt.rn.bf16x2.f32 %0, %1, %2;" : "=r"(r) : "f"(hi), "f"(lo));
    return r;
}
// exp(x) on fma/alu pipes only (no MUFU). Caller clamps x >= -60.
static __device__ __forceinline__ float fexp(float x) {
    const float L2E = 1.4426950408889634f;
    float t = fmaf(x, L2E, 12582912.0f);          // 1.5*2^23: rounds to int
    int   in = __float_as_int(t);
    float n  = t - 12582912.0f;
    float z  = fmaf(x, L2E, -n);                  // frac in [-0.5, 0.5]
    float w  = z * 0.6931471805599453f;
    float p  = fmaf(w, 8.3333333e-3f, 4.1666667e-2f);
    p = fmaf(p, w, 0.16666667f);
    p = fmaf(p, w, 0.5f);
    p = fmaf(p, w, 1.0f);
    p = fmaf(p, w, 1.0f);
    return __int_as_float(__float_as_int(p) + (in << 23));
}
static __device__ __forceinline__ void mma_tf32(float* d, const uint32_t* a,
                                                const uint32_t* b) {
    asm volatile(
        "mma.sync.aligned.m16n8k8.row.col.f32.tf32.tf32.f32 "
        "{%0,%1,%2,%3}, {%4,%5,%6,%7}, {%8,%9}, {%0,%1,%2,%3};"
        : "+f"(d[0]), "+f"(d[1]), "+f"(d[2]), "+f"(d[3])
        : "r"(a[0]), "r"(a[1]), "r"(a[2]), "r"(a[3]), "r"(b[0]), "r"(b[1]));
}
static __device__ __forceinline__ void mma_bf16(float* d, const uint32_t* a,
                                                const uint32_t* b) {
    asm volatile(
        "mma.sync.aligned.m16n8k16.row.col.f32.bf16.bf16.f32 "
        "{%0,%1,%2,%3}, {%4,%5,%6,%7}, {%8,%9}, {%0,%1,%2,%3};"
        : "+f"(d[0]), "+f"(d[1]), "+f"(d[2]), "+f"(d[3])
        : "r"(a[0]), "r"(a[1]), "r"(a[2]), "r"(a[3]), "r"(b[0]), "r"(b[1]));
}

// Pre-kernel: fold mask into cov (one streaming pass, high occupancy)
__global__ __launch_bounds__(256, 8)
void covmask_kernel(const float* __restrict__ cov, const int* __restrict__ mask)
{
    size_t i = ((size_t)blockIdx.x * 256 + threadIdx.x) * 4;
    float4 c = *(const float4*)(cov + i);
    int4   m = *(const int4*)(mask + i);
    float4 o;
    o.x = m.x ? c.x : -30000.0f;
    o.y = m.y ? c.y : -30000.0f;
    o.z = m.z ? c.z : -30000.0f;
    o.w = m.w ? c.w : -30000.0f;
    *(float4*)(g_covm + i) = o;
}

__global__ __launch_bounds__(NT, 2)
void attn_mma_kernel(const float* __restrict__ q,
                     const float* __restrict__ k,
                     const float* __restrict__ v,
                     const float* __restrict__ lambda_w,
                     float* __restrict__ out,      // [B,H,S,D]
                     float* __restrict__ attn)     // [B,H,S,S]
{
    extern __shared__ uint32_t sw[];
    uint32_t* QW  = sw + W_Q;
    uint32_t* KTW = sw + W_KT;
    uint32_t* VHW = sw + W_VH;
    uint32_t* VLW = sw + W_VL;
    uint32_t* EHW = sw + W_EH;
    uint32_t* ELW = sw + W_EL;
    float*    rs  = (float*)(sw + W_RS);

    const int h     = blockIdx.x;   // innermost -> 8 heads share covm in L2
    const int mtile = blockIdx.y;
    const int b     = blockIdx.z;
    const int bh    = b * Hq + h;
    const int tid   = threadIdx.x;
    const int wid   = tid >> 5;
    const int lane  = tid & 31;
    const int lg    = lane >> 2;    // group 0..7
    const int lt    = lane & 3;     // 0..3

    const int warp_m = wid & 3;     // row group (32 rows)
    const int warp_n = wid >> 2;    // 0..1: score col half / AV d half
    const int rm = warp_m * 32;
    const int cn = warp_n * 32;
    const int dn = warp_n * 32;

    const float lam  = lambda_w[h];
    const float wcov = lam / (lam + 1.0f);
    const float sqk  = 1.0f / ((lam + 1.0f) * TEMP);

    const float* qg    = q + ((size_t)bh * Sq + (size_t)mtile * BM) * Dq;
    const float* kg    = k + (size_t)bh * Sq * Dq;
    const float* vg    = v + (size_t)bh * Sq * Dq;
    const float* covg  = g_covm + ((size_t)b * Sq + (size_t)mtile * BM) * Sq;
    float*       attng = attn + ((size_t)bh * Sq + (size_t)mtile * BM) * Sq;
    float*       outg  = out  + ((size_t)bh * Sq + (size_t)mtile * BM) * Dq;

    // ---- fill q smem (tf32), once ----
    {
#pragma unroll
        for (int it = 0; it < 8; it++) {
            int idx = tid + it * NT;        // 2048 float4
            int r  = idx >> 4;
            int c4 = (idx & 15) << 2;
            float4 f = *(const float4*)&qg[r * Dq + c4];
            uint4 o;
            o.x = f2tf32(f.x); o.y = f2tf32(f.y);
            o.z = f2tf32(f.z); o.w = f2tf32(f.w);
            *(uint4*)&QW[r * 68 + c4] = o;
        }
    }

    float oacc[2][4][4];    // AV accumulators (32 rows x 32 d per warp)
#pragma unroll
    for (int mi = 0; mi < 2; mi++)
#pragma unroll
        for (int nf = 0; nf < 4; nf++)
#pragma unroll
            for (int c = 0; c < 4; c++) oacc[mi][nf][c] = 0.0f;
    float rowsum[4] = {0.0f, 0.0f, 0.0f, 0.0f};

    for (int nt = 0; nt < Sq / BN; nt++) {
        const int t0 = nt * BN;
        __syncthreads();   // protect k/v/e smem from previous AV reads

        // ---- fill k^T (tf32): 64 t x 64 d ----
#pragma unroll
        for (int it = 0; it < 4; it++) {
            int idx = tid + it * NT;        // 1024 float4
            int t  = idx & 63;
            int c4 = (idx >> 6) << 2;
            float4 f = *(const float4*)&kg[(size_t)(t0 + t) * Dq + c4];
            KTW[(c4 + 0) * KTS + t] = f2tf32(f.x);
            KTW[(c4 + 1) * KTS + t] = f2tf32(f.y);
            KTW[(c4 + 2) * KTS + t] = f2tf32(f.z);
            KTW[(c4 + 3) * KTS + t] = f2tf32(f.w);
        }
        // ---- fill v^T split-bf16 (paired t): 32 tp x 64 d ----
#pragma unroll
        for (int it = 0; it < 2; it++) {
            int idx = tid + it * NT;        // 512 items: 32 tp x 16 d4
            int tp = idx & 31;
            int d4 = (idx >> 5) << 2;
            float4 v0 = *(const float4*)&vg[(size_t)(t0 + 2 * tp) * Dq + d4];
            float4 v1 = *(const float4*)&vg[(size_t)(t0 + 2 * tp + 1) * Dq + d4];
            const float e0[4] = {v0.x, v0.y, v0.z, v0.w};
            const float e1[4] = {v1.x, v1.y, v1.z, v1.w};
#pragma unroll
            for (int i = 0; i < 4; i++) {
                uint32_t hp = bf16x2(e1[i], e0[i]);
                float f0 = __uint_as_float(hp << 16);
                float f1 = __uint_as_float(hp & 0xffff0000u);
                uint32_t lp = bf16x2(e1[i] - f1, e0[i] - f0);
                VHW[(d4 + i) * EVS + tp] = hp;
                VLW[(d4 + i) * EVS + tp] = lp;
            }
        }
        __syncthreads();

        // ---- scores: warp tile 32 rows x 32 cols, tf32 mma ----
        float acc[2][4][4];
#pragma unroll
        for (int mi = 0; mi < 2; mi++)
#pragma unroll
            for (int ni = 0; ni < 4; ni++)
#pragma unroll
                for (int c = 0; c < 4; c++) acc[mi][ni][c] = 0.0f;

#pragma unroll
        for (int ks = 0; ks < 8; ks++) {
            const int kd = ks * 8;
            uint32_t a[2][4], bb[4][2];
#pragma unroll
            for (int mi = 0; mi < 2; mi++) {
                const uint32_t* q0 = QW + (rm + mi * 16 + lg) * 68 + kd + lt;
                a[mi][0] = q0[0];
                a[mi][1] = q0[8 * 68];
                a[mi][2] = q0[4];
                a[mi][3] = q0[8 * 68 + 4];
            }
#pragma unroll
            for (int ni = 0; ni < 4; ni++) {
                const uint32_t* kp = KTW + (kd + lt) * KTS + cn + ni * 8 + lg;
                bb[ni][0] = kp[0];
                bb[ni][1] = kp[4 * KTS];
            }
#pragma unroll
            for (int mi = 0; mi < 2; mi++)
#pragma unroll
                for (int ni = 0; ni < 4; ni++)
                    mma_tf32(acc[mi][ni], a[mi], bb[ni]);
        }

        // ---- epilogue: blend (pre-masked cov), exp, attn store, pack e ----
#pragma unroll
        for (int mi = 0; mi < 2; mi++) {
#pragma unroll
            for (int rh = 0; rh < 2; rh++) {
                const int r = rm + mi * 16 + lg + rh * 8;
                const float* cr = covg  + (size_t)r * Sq + t0;
                float*       ar = attng + (size_t)r * Sq + t0;
                uint32_t* ehr = EHW + r * EVS;
                uint32_t* elr = ELW + r * EVS;
                // hoist the 4 independent cov loads for MLP
                float2 cv[4];
#pragma unroll
                for (int ni = 0; ni < 4; ni++)
                    cv[ni] = *(const float2*)(cr + cn + ni * 8 + 2 * lt);
                float rsacc = 0.0f;
#pragma unroll
                for (int ni = 0; ni < 4; ni++) {
                    const int c = cn + ni * 8 + 2 * lt;
                    float s0 = acc[mi][ni][rh * 2 + 0];
                    float s1 = acc[mi][ni][rh * 2 + 1];
                    float l0 = fmaxf(fmaf(sqk, s0, wcov * cv[ni].x), -60.0f);
                    float l1 = fmaxf(fmaf(sqk, s1, wcov * cv[ni].y), -60.0f);
                    float e0 = fexp(l0);
                    float e1 = fexp(l1);
                    rsacc += e0 + e1;
                    *(float2*)(ar + c) = make_float2(e0, e1);
                    uint32_t hp = bf16x2(e1, e0);
                    float f0 = __uint_as_float(hp << 16);
                    float f1 = __uint_as_float(hp & 0xffff0000u);
                    uint32_t lp = bf16x2(e1 - f1, e0 - f0);
                    const int tpl = c >> 1;
                    ehr[tpl] = hp;
                    elr[tpl] = lp;
                }
                rowsum[mi * 2 + rh] += rsacc;
            }
        }
        __syncthreads();

        // ---- AV: warp tile 32 rows x 32 d, k=64 via 4 k16 steps ----
#pragma unroll
        for (int ks = 0; ks < 4; ks++) {
            const int tpb = ks * 8 + lt;
            uint32_t ah[2][4], al[2][4], bh[4][2], bl[4][2];
#pragma unroll
            for (int mi = 0; mi < 2; mi++) {
                const int base = (rm + mi * 16 + lg) * EVS + tpb;
                ah[mi][0] = EHW[base];
                ah[mi][1] = EHW[base + 8 * EVS];
                ah[mi][2] = EHW[base + 4];
                ah[mi][3] = EHW[base + 8 * EVS + 4];
                al[mi][0] = ELW[base];
                al[mi][1] = ELW[base + 8 * EVS];
                al[mi][2] = ELW[base + 4];
                al[mi][3] = ELW[base + 8 * EVS + 4];
            }
#pragma unroll
            for (int nf = 0; nf < 4; nf++) {
                const int base = (dn + nf * 8 + lg) * EVS + tpb;
                bh[nf][0] = VHW[base];
                bh[nf][1] = VHW[base + 4];
                bl[nf][0] = VLW[base];
                bl[nf][1] = VLW[base + 4];
            }
#pragma unroll
            for (int mi = 0; mi < 2; mi++)
#pragma unroll
                for (int nf = 0; nf < 4; nf++) {
                    mma_bf16(oacc[mi][nf], ah[mi], bh[nf]);
                    mma_bf16(oacc[mi][nf], ah[mi], bl[nf]);
                    mma_bf16(oacc[mi][nf], al[mi], bh[nf]);
                }
        }
    }

    // ---- rowsum: reduce over lane&3 (lanes sharing a row) ----
#pragma unroll
    for (int i = 0; i < 4; i++) {
        rowsum[i] += __shfl_xor_sync(0xffffffffu, rowsum[i], 1);
        rowsum[i] += __shfl_xor_sync(0xffffffffu, rowsum[i], 2);
    }
    if (lt == 0) {
#pragma unroll
        for (int mi = 0; mi < 2; mi++)
#pragma unroll
            for (int rh = 0; rh < 2; rh++)
                rs[warp_n * 128 + rm + mi * 16 + lg + rh * 8] = rowsum[mi * 2 + rh];
    }
    __syncthreads();

    // ---- write normalized output ----
#pragma unroll
    for (int mi = 0; mi < 2; mi++) {
#pragma unroll
        for (int rh = 0; rh < 2; rh++) {
            const int r = rm + mi * 16 + lg + rh * 8;
            const float iv = 1.0f / (rs[r] + rs[128 + r]);
#pragma unroll
            for (int nf = 0; nf < 4; nf++) {
                const int d = dn + nf * 8 + 2 * lt;
                float2 o;
                o.x = oacc[mi][nf][rh * 2 + 0] * iv;
                o.y = oacc[mi][nf][rh * 2 + 1] * iv;
                *(float2*)(outg + (size_t)r * Dq + d) = o;
            }
        }
    }

    // ---- fused normalize tail: scale this block's attn slice ----
    const int rlane = tid >> 7;          // 0..1
    const int ci    = tid & 127;         // float4 col
#pragma unroll 2
    for (int rb = 0; rb < 64; rb++) {
        const int r = rb * 2 + rlane;
        const float iv = 1.0f / (rs[r] + rs[128 + r]);
        float4* arow = (float4*)(attng + (size_t)r * Sq);
        float4 x0 = arow[ci];
        float4 x1 = arow[ci + 128];
        float4 x2 = arow[ci + 256];
        float4 x3 = arow[ci + 384];
        x0.x *= iv; x0.y *= iv; x0.z *= iv; x0.w *= iv;
        x1.x *= iv; x1.y *= iv; x1.z *= iv; x1.w *= iv;
        x2.x *= iv; x2.y *= iv; x2.z *= iv; x2.w *= iv;
        x3.x *= iv; x3.y *= iv; x3.z *= iv; x3.w *= iv;
        arow[ci]       = x0;
        arow[ci + 128] = x1;
        arow[ci + 256] = x2;
        arow[ci + 384] = x3;
    }
}

extern "C" void kernel_launch(void* const* d_in, const int* in_sizes, int n_in,
                              void* d_out, int out_size)
{
    const float* q    = (const float*)d_in[0];
    const float* k    = (const float*)d_in[1];
    const float* v    = (const float*)d_in[2];
    const float* cov  = (const float*)d_in[3];
    const float* lam  = (const float*)d_in[4];
    const int*   mask = (const int*)d_in[5];

    float* out  = (float*)d_out;                          // [B,H,S,D]
    float* attn = out + (size_t)Bq * Hq * Sq * Dq;        // [B,H,S,S]

    // pass 0: fold mask into cov (streaming, ~25 us)
    const size_t n4 = (size_t)Bq * Sq * Sq / 4;           // 2,097,152 float4
    covmask_kernel<<<(unsigned)(n4 / 256), 256>>>(cov, mask);

    cudaFuncSetAttribute(attn_mma_kernel,
                         cudaFuncAttributeMaxDynamicSharedMemorySize, SMEM_BYTES);
    dim3 grid(Hq, Sq / BM, Bq);  // h innermost: heads share covm in L2
    attn_mma_kernel<<<grid, NT, SMEM_BYTES>>>(q, k, v, lam, out, attn);
}

// round 10
// speedup vs baseline: 1.6822x; 1.0589x over previous
#include <cuda_runtime.h>
#include <cstdint>

#define Bq 2
#define Hq 8
#define Sq 2048
#define Dq 64
#define TEMP 8.0f

#define BM 128
#define BN 64
#define NT 512
#define NTILES (Sq / BN)   // 32

// smem word offsets
#define W_Q   0                      // q tf32 [128][68]
#define W_K0  8704                   // k raw f32 [64][68] natural [t][d], buf 0
#define W_K1  13056                  // buf 1
#define W_VR0 17408                  // v raw f32 [64][68], buf 0
#define W_VR1 21760                  // buf 1
#define W_VH  26112                  // v^T hi bf16x2 [64][36] ([d][tpair])
#define W_VL  28416                  // v^T lo bf16x2 [64][36]
#define W_EH  30720                  // e hi bf16x2 [128][36] ([row][tpair])
#define W_EL  35328                  // e lo bf16x2 [128][36]
#define W_RS  39936                  // rowsum [4][128] floats
#define SMEM_WORDS 40448
#define SMEM_BYTES (SMEM_WORDS * 4)  // 161792 B -> 1 CTA/SM

#define KVS 68     // K / Vraw row stride (words)
#define EVS 36     // row stride (words) for VH/VL/EH/EL

// masked-cov scratch: covm = mask ? cov : -3e4   (33.5 MB)
__device__ float g_covm[(size_t)Bq * Sq * Sq];

static __device__ __forceinline__ uint32_t f2tf32(float f) {
    uint32_t r;
    asm("cvt.rna.tf32.f32 %0, %1;" : "=r"(r) : "f"(f));
    return r;
}
static __device__ __forceinline__ uint32_t bf16x2(float hi, float lo) {
    uint32_t r;
    asm("cvt.rn.bf16x2.f32 %0, %1, %2;" : "=r"(r) : "f"(hi), "f"(lo));
    return r;
}
// exp(x) on fma/alu pipes only (no MUFU). Caller clamps x >= -60.
static __device__ __forceinline__ float fexp(float x) {
    const float L2E = 1.4426950408889634f;
    float t = fmaf(x, L2E, 12582912.0f);          // 1.5*2^23: rounds to int
    int   in = __float_as_int(t);
    float n  = t - 12582912.0f;
    float z  = fmaf(x, L2E, -n);                  // frac in [-0.5, 0.5]
    float w  = z * 0.6931471805599453f;
    float p  = fmaf(w, 8.3333333e-3f, 4.1666667e-2f);
    p = fmaf(p, w, 0.16666667f);
    p = fmaf(p, w, 0.5f);
    p = fmaf(p, w, 1.0f);
    p = fmaf(p, w, 1.0f);
    return __int_as_float(__float_as_int(p) + (in << 23));
}
static __device__ __forceinline__ void mma_tf32(float* d, const uint32_t* a,
                                                const uint32_t* b) {
    asm volatile(
        "mma.sync.aligned.m16n8k8.row.col.f32.tf32.tf32.f32 "
        "{%0,%1,%2,%3}, {%4,%5,%6,%7}, {%8,%9}, {%0,%1,%2,%3};"
        : "+f"(d[0]), "+f"(d[1]), "+f"(d[2]), "+f"(d[3])
        : "r"(a[0]), "r"(a[1]), "r"(a[2]), "r"(a[3]), "r"(b[0]), "r"(b[1]));
}
static __device__ __forceinline__ void mma_bf16(float* d, const uint32_t* a,
                                                const uint32_t* b) {
    asm volatile(
        "mma.sync.aligned.m16n8k16.row.col.f32.bf16.bf16.f32 "
        "{%0,%1,%2,%3}, {%4,%5,%6,%7}, {%8,%9}, {%0,%1,%2,%3};"
        : "+f"(d[0]), "+f"(d[1]), "+f"(d[2]), "+f"(d[3])
        : "r"(a[0]), "r"(a[1]), "r"(a[2]), "r"(a[3]), "r"(b[0]), "r"(b[1]));
}
static __device__ __forceinline__ void cp16(uint32_t dst, const void* src) {
    asm volatile("cp.async.cg.shared.global [%0], [%1], 16;"
                 :: "r"(dst), "l"(src) : "memory");
}

// Pre-kernel: fold mask into cov (one streaming pass, high occupancy)
__global__ __launch_bounds__(256, 8)
void covmask_kernel(const float* __restrict__ cov, const int* __restrict__ mask)
{
    size_t i = ((size_t)blockIdx.x * 256 + threadIdx.x) * 4;
    float4 c = *(const float4*)(cov + i);
    int4   m = *(const int4*)(mask + i);
    float4 o;
    o.x = m.x ? c.x : -30000.0f;
    o.y = m.y ? c.y : -30000.0f;
    o.z = m.z ? c.z : -30000.0f;
    o.w = m.w ? c.w : -30000.0f;
    *(float4*)(g_covm + i) = o;
}

__global__ __launch_bounds__(NT, 1)
void attn_mma_kernel(const float* __restrict__ q,
                     const float* __restrict__ k,
                     const float* __restrict__ v,
                     const float* __restrict__ lambda_w,
                     float* __restrict__ out,      // [B,H,S,D]
                     float* __restrict__ attn)     // [B,H,S,S]
{
    extern __shared__ uint32_t sw[];
    const uint32_t sbase = (uint32_t)__cvta_generic_to_shared(sw);
    uint32_t* QW  = sw + W_Q;
    uint32_t* VHW = sw + W_VH;
    uint32_t* VLW = sw + W_VL;
    uint32_t* EHW = sw + W_EH;
    uint32_t* ELW = sw + W_EL;
    float*    rs  = (float*)(sw + W_RS);

    const int h     = blockIdx.x;   // innermost -> heads share covm in L2
    const int mpair = blockIdx.y;   // 2 mtiles per CTA
    const int b     = blockIdx.z;
    const int bh    = b * Hq + h;
    const int tid   = threadIdx.x;
    const int wid   = tid >> 5;
    const int lane  = tid & 31;
    const int lg    = lane >> 2;    // group 0..7
    const int lt    = lane & 3;     // 0..3

    const int warp_m = wid & 3;     // row group (32 rows)
    const int warp_n = wid >> 2;    // 0..3: 16-col / 16-d slice
    const int rm = warp_m * 32;
    const int cn = warp_n * 16;
    const int dn = warp_n * 16;

    const float lam  = lambda_w[h];
    const float wcov = lam / (lam + 1.0f);
    const float sqk  = 1.0f / ((lam + 1.0f) * TEMP);

    const float* kg = k + (size_t)bh * Sq * Dq;
    const float* vg = v + (size_t)bh * Sq * Dq;

    for (int m = 0; m < 2; m++) {
        const int mtile = mpair * 2 + m;
        const float* qg    = q + ((size_t)bh * Sq + (size_t)mtile * BM) * Dq;
        const float* covg  = g_covm + ((size_t)b * Sq + (size_t)mtile * BM) * Sq;
        float*       attng = attn + ((size_t)bh * Sq + (size_t)mtile * BM) * Sq;
        float*       outg  = out  + ((size_t)bh * Sq + (size_t)mtile * BM) * Dq;

        // ---- prefetch tile 0 (K + Vraw) ----
        {
#pragma unroll
            for (int it = 0; it < 2; it++) {
                int idx = tid + it * NT;   // 1024 16B segs each
                int t   = idx >> 4;
                int seg = idx & 15;
                cp16(sbase + (uint32_t)(W_K0  + t * KVS + seg * 4) * 4,
                     kg + (size_t)t * Dq + seg * 4);
                cp16(sbase + (uint32_t)(W_VR0 + t * KVS + seg * 4) * 4,
                     vg + (size_t)t * Dq + seg * 4);
            }
            asm volatile("cp.async.commit_group;" ::: "memory");
        }

        __syncthreads();   // QW free (previous mtile done reading)
        // ---- fill q smem (tf32) ----
#pragma unroll
        for (int it = 0; it < 4; it++) {
            int idx = tid + it * NT;        // 2048 float4
            int r  = idx >> 4;
            int c4 = (idx & 15) << 2;
            float4 f = *(const float4*)&qg[r * Dq + c4];
            uint4 o;
            o.x = f2tf32(f.x); o.y = f2tf32(f.y);
            o.z = f2tf32(f.z); o.w = f2tf32(f.w);
            *(uint4*)&QW[r * 68 + c4] = o;
        }

        float oacc[2][2][4];
#pragma unroll
        for (int mi = 0; mi < 2; mi++)
#pragma unroll
            for (int nf = 0; nf < 2; nf++)
#pragma unroll
                for (int c = 0; c < 4; c++) oacc[mi][nf][c] = 0.0f;
        float rowsum[4] = {0.0f, 0.0f, 0.0f, 0.0f};

        for (int nt = 0; nt < NTILES; nt++) {
            const int buf = nt & 1;
            const int kof = buf ? W_K1 : W_K0;
            const int vof = buf ? W_VR1 : W_VR0;
            const int t0  = nt * BN;

            // ---- prefetch next tile, then wait for current ----
            if (nt + 1 < NTILES) {
                const int kofn = buf ? W_K0 : W_K1;
                const int vofn = buf ? W_VR0 : W_VR1;
                const float* kn = kg + (size_t)(t0 + BN) * Dq;
                const float* vn = vg + (size_t)(t0 + BN) * Dq;
#pragma unroll
                for (int it = 0; it < 2; it++) {
                    int idx = tid + it * NT;
                    int t   = idx >> 4;
                    int seg = idx & 15;
                    cp16(sbase + (uint32_t)(kofn + t * KVS + seg * 4) * 4,
                         kn + (size_t)t * Dq + seg * 4);
                    cp16(sbase + (uint32_t)(vofn + t * KVS + seg * 4) * 4,
                         vn + (size_t)t * Dq + seg * 4);
                }
                asm volatile("cp.async.commit_group;" ::: "memory");
                asm volatile("cp.async.wait_group 1;" ::: "memory");
            } else {
                asm volatile("cp.async.wait_group 0;" ::: "memory");
            }
            __syncthreads();   // cp data visible; prev AV done with VH/VL/E

            // ---- convert Vraw -> split-bf16 VH/VL (1 item/thread) ----
            {
                const uint32_t* VR = sw + vof;
                int tp = tid & 31;
                int d4 = (tid >> 5) << 2;
                float4 v0 = *(const float4*)&VR[(2 * tp)     * KVS + d4];
                float4 v1 = *(const float4*)&VR[(2 * tp + 1) * KVS + d4];
                const float e0[4] = {v0.x, v0.y, v0.z, v0.w};
                const float e1[4] = {v1.x, v1.y, v1.z, v1.w};
#pragma unroll
                for (int i = 0; i < 4; i++) {
                    uint32_t hp = bf16x2(e1[i], e0[i]);
                    float f0 = __uint_as_float(hp << 16);
                    float f1 = __uint_as_float(hp & 0xffff0000u);
                    uint32_t lp = bf16x2(e1[i] - f1, e0[i] - f0);
                    VHW[(d4 + i) * EVS + tp] = hp;
                    VLW[(d4 + i) * EVS + tp] = lp;
                }
            }
            __syncthreads();

            // ---- cov prefetch (hidden behind QK MMA) ----
            float2 cv[2][2][2];
#pragma unroll
            for (int mi = 0; mi < 2; mi++)
#pragma unroll
                for (int rh = 0; rh < 2; rh++) {
                    const int r = rm + mi * 16 + lg + rh * 8;
#pragma unroll
                    for (int ni = 0; ni < 2; ni++)
                        cv[mi][rh][ni] = *(const float2*)
                            (covg + (size_t)r * Sq + t0 + cn + ni * 8 + 2 * lt);
                }

            // ---- scores: warp tile 32 rows x 16 cols, tf32 mma ----
            // K in natural [t][d] layout; raw f32 bits used as tf32 (trunc)
            const uint32_t* KB = sw + kof;
            float acc[2][2][4];
#pragma unroll
            for (int mi = 0; mi < 2; mi++)
#pragma unroll
                for (int ni = 0; ni < 2; ni++)
#pragma unroll
                    for (int c = 0; c < 4; c++) acc[mi][ni][c] = 0.0f;

#pragma unroll
            for (int ks = 0; ks < 8; ks++) {
                const int kd = ks * 8;
                uint32_t a[2][4], bb[2][2];
#pragma unroll
                for (int mi = 0; mi < 2; mi++) {
                    const uint32_t* q0 = QW + (rm + mi * 16 + lg) * 68 + kd + lt;
                    a[mi][0] = q0[0];
                    a[mi][1] = q0[8 * 68];
                    a[mi][2] = q0[4];
                    a[mi][3] = q0[8 * 68 + 4];
                }
#pragma unroll
                for (int ni = 0; ni < 2; ni++) {
                    const uint32_t* kp = KB + (cn + ni * 8 + lg) * KVS + kd + lt;
                    bb[ni][0] = kp[0];
                    bb[ni][1] = kp[4];
                }
#pragma unroll
                for (int mi = 0; mi < 2; mi++)
#pragma unroll
                    for (int ni = 0; ni < 2; ni++)
                        mma_tf32(acc[mi][ni], a[mi], bb[ni]);
            }

            // ---- epilogue: blend, exp, attn store, pack e ----
#pragma unroll
            for (int mi = 0; mi < 2; mi++) {
#pragma unroll
                for (int rh = 0; rh < 2; rh++) {
                    const int r = rm + mi * 16 + lg + rh * 8;
                    float* ar = attng + (size_t)r * Sq + t0;
                    uint32_t* ehr = EHW + r * EVS;
                    uint32_t* elr = ELW + r * EVS;
                    float rsacc = 0.0f;
#pragma unroll
                    for (int ni = 0; ni < 2; ni++) {
                        const int c = cn + ni * 8 + 2 * lt;
                        float s0 = acc[mi][ni][rh * 2 + 0];
                        float s1 = acc[mi][ni][rh * 2 + 1];
                        float l0 = fmaxf(fmaf(sqk, s0, wcov * cv[mi][rh][ni].x), -60.0f);
                        float l1 = fmaxf(fmaf(sqk, s1, wcov * cv[mi][rh][ni].y), -60.0f);
                        float e0 = fexp(l0);
                        float e1 = fexp(l1);
                        rsacc += e0 + e1;
                        *(float2*)(ar + c) = make_float2(e0, e1);
                        uint32_t hp = bf16x2(e1, e0);
                        float f0 = __uint_as_float(hp << 16);
                        float f1 = __uint_as_float(hp & 0xffff0000u);
                        uint32_t lp = bf16x2(e1 - f1, e0 - f0);
                        const int tpl = c >> 1;
                        ehr[tpl] = hp;
                        elr[tpl] = lp;
                    }
                    rowsum[mi * 2 + rh] += rsacc;
                }
            }
            __syncthreads();

            // ---- AV: warp tile 32 rows x 16 d, k=64 via 4 k16 steps ----
#pragma unroll
            for (int ks = 0; ks < 4; ks++) {
                const int tpb = ks * 8 + lt;
                uint32_t ah[2][4], al[2][4], bh[2][2], bl[2][2];
#pragma unroll
                for (int mi = 0; mi < 2; mi++) {
                    const int base = (rm + mi * 16 + lg) * EVS + tpb;
                    ah[mi][0] = EHW[base];
                    ah[mi][1] = EHW[base + 8 * EVS];
                    ah[mi][2] = EHW[base + 4];
                    ah[mi][3] = EHW[base + 8 * EVS + 4];
                    al[mi][0] = ELW[base];
                    al[mi][1] = ELW[base + 8 * EVS];
                    al[mi][2] = ELW[base + 4];
                    al[mi][3] = ELW[base + 8 * EVS + 4];
                }
#pragma unroll
                for (int nf = 0; nf < 2; nf++) {
                    const int base = (dn + nf * 8 + lg) * EVS + tpb;
                    bh[nf][0] = VHW[base];
                    bh[nf][1] = VHW[base + 4];
                    bl[nf][0] = VLW[base];
                    bl[nf][1] = VLW[base + 4];
                }
#pragma unroll
                for (int mi = 0; mi < 2; mi++)
#pragma unroll
                    for (int nf = 0; nf < 2; nf++) {
                        mma_bf16(oacc[mi][nf], ah[mi], bh[nf]);
                        mma_bf16(oacc[mi][nf], ah[mi], bl[nf]);
                        mma_bf16(oacc[mi][nf], al[mi], bh[nf]);
                    }
            }
        }

        // ---- rowsum: reduce over lane&3, store partials ----
#pragma unroll
        for (int i = 0; i < 4; i++) {
            rowsum[i] += __shfl_xor_sync(0xffffffffu, rowsum[i], 1);
            rowsum[i] += __shfl_xor_sync(0xffffffffu, rowsum[i], 2);
        }
        if (lt == 0) {
#pragma unroll
            for (int mi = 0; mi < 2; mi++)
#pragma unroll
                for (int rh = 0; rh < 2; rh++)
                    rs[warp_n * 128 + rm + mi * 16 + lg + rh * 8] = rowsum[mi * 2 + rh];
        }
        __syncthreads();

        // ---- write normalized output ----
#pragma unroll
        for (int mi = 0; mi < 2; mi++) {
#pragma unroll
            for (int rh = 0; rh < 2; rh++) {
                const int r = rm + mi * 16 + lg + rh * 8;
                const float iv = 1.0f /
                    (rs[r] + rs[128 + r] + rs[256 + r] + rs[384 + r]);
#pragma unroll
                for (int nf = 0; nf < 2; nf++) {
                    const int d = dn + nf * 8 + 2 * lt;
                    float2 o;
                    o.x = oacc[mi][nf][rh * 2 + 0] * iv;
                    o.y = oacc[mi][nf][rh * 2 + 1] * iv;
                    *(float2*)(outg + (size_t)r * Dq + d) = o;
                }
            }
        }

        // ---- fused normalize tail: scale this mtile's attn slice ----
        {
            const int rlane = tid >> 7;          // 0..3
            const int ci    = tid & 127;         // float4 col
#pragma unroll 2
            for (int rb = 0; rb < 32; rb++) {
                const int r = rb * 4 + rlane;
                const float iv = 1.0f /
                    (rs[r] + rs[128 + r] + rs[256 + r] + rs[384 + r]);
                float4* arow = (float4*)(attng + (size_t)r * Sq);
                float4 x0 = arow[ci];
                float4 x1 = arow[ci + 128];
                float4 x2 = arow[ci + 256];
                float4 x3 = arow[ci + 384];
                x0.x *= iv; x0.y *= iv; x0.z *= iv; x0.w *= iv;
                x1.x *= iv; x1.y *= iv; x1.z *= iv; x1.w *= iv;
                x2.x *= iv; x2.y *= iv; x2.z *= iv; x2.w *= iv;
                x3.x *= iv; x3.y *= iv; x3.z *= iv; x3.w *= iv;
                arow[ci]       = x0;
                arow[ci + 128] = x1;
                arow[ci + 256] = x2;
                arow[ci + 384] = x3;
            }
        }
    }
}

extern "C" void kernel_launch(void* const* d_in, const int* in_sizes, int n_in,
                              void* d_out, int out_size)
{
    const float* q    = (const float*)d_in[0];
    const float* k    = (const float*)d_in[1];
    const float* v    = (const float*)d_in[2];
    const float* cov  = (const float*)d_in[3];
    const float* lam  = (const float*)d_in[4];
    const int*   mask = (const int*)d_in[5];

    float* out  = (float*)d_out;                          // [B,H,S,D]
    float* attn = out + (size_t)Bq * Hq * Sq * Dq;        // [B,H,S,S]

    // pass 0: fold mask into cov (streaming)
    const size_t n4 = (size_t)Bq * Sq * Sq / 4;
    covmask_kernel<<<(unsigned)(n4 / 256), 256>>>(cov, mask);

    cudaFuncSetAttribute(attn_mma_kernel,
                         cudaFuncAttributeMaxDynamicSharedMemorySize, SMEM_BYTES);
    dim3 grid(Hq, Sq / BM / 2, Bq);  // (8, 8, 2) = 128 CTAs, single wave
    attn_mma_kernel<<<grid, NT, SMEM_BYTES>>>(q, k, v, lam, out, attn);
}